// round 10
// baseline (speedup 1.0000x reference)
#include <cuda_runtime.h>
#include <cstdint>

// out[nat, 48] = segment_sum(x*switch, src) - segment_sum(x*switch, dst)
// E = 1.6M, D = 48, nat = 50k.
//
// R4-R9 established: pure-atomic floor = LTS atomic-unit rate (1 x 16B RMW
// op/slice/cyc -> ~106us for 38.4M ops). To go below it, this kernel splits
// the edge set:
//   60% edges -> proven red.v4 atomic path (uses the LTS atomic unit)
//   40% edges -> binned register-gather path (uses only the read datapath):
//       K1 bins endpoint records per node (CAP=64, red fallback on overflow)
//       K2 runs BOTH halves concurrently (interleaved blocks): gather warps
//          accumulate their nodes in registers, plain-store to scratch
//       K3 merges scratch into out
// The two halves exercise disjoint LTS sub-units and overlap.

#define D_FEAT 48
#define VPE 12                 // float4 per 48-float row
#define NAT_MAX 50176
#define CAP 64

__device__ int   g_cnt[NAT_MAX];
__device__ int   g_bins[NAT_MAX * CAP];
__device__ float g_scr[NAT_MAX * D_FEAT];

__device__ __forceinline__ void red_v4(float* p, float a, float b, float c, float d) {
    asm volatile("red.global.add.v4.f32 [%0], {%1,%2,%3,%4};"
                 :: "l"(p), "f"(a), "f"(b), "f"(c), "f"(d) : "memory");
}

// ---- K1: bin the gather-half endpoints (edge ids + sign bit) ----
__global__ void __launch_bounds__(256)
bin_kernel(const int* __restrict__ esrc, const int* __restrict__ edst,
           const float4* __restrict__ x4, const float* __restrict__ sw,
           float* __restrict__ out, int e_g) {
    unsigned t = blockIdx.x * 256u + threadIdx.x;
    if (t >= 2u * (unsigned)e_g) return;
    bool isdst = t >= (unsigned)e_g;
    unsigned e = isdst ? t - (unsigned)e_g : t;
    int node = isdst ? __ldg(edst + e) : __ldg(esrc + e);
    int pos = atomicAdd(&g_cnt[node], 1);
    if (pos < CAP) {
        g_bins[node * CAP + pos] = (int)(e | (isdst ? 0x80000000u : 0u));
    } else {
        // overflow fallback (statistically ~never): direct atomic reduce
        float s = __ldg(sw + e);
        if (isdst) s = -s;
        #pragma unroll
        for (int c = 0; c < VPE; c++) {
            float4 v = __ldcs(x4 + (size_t)e * VPE + c);
            red_v4(out + (size_t)node * D_FEAT + c * 4, v.x*s, v.y*s, v.z*s, v.w*s);
        }
    }
}

// ---- K2: concurrent atomic-scatter (60%) + register-gather (40%) ----
__global__ void __launch_bounds__(128)
hybrid_kernel(const float4* __restrict__ x4,
              const float2* __restrict__ sw2a,   // pre-offset to atomic half
              const int2* __restrict__ esrc2a,
              const int2* __restrict__ edst2a,
              const float* __restrict__ sw,
              float* __restrict__ out,
              int n_pairs, int e_g, int nat,
              int n_gblocks, int n_blocks_total) {
    unsigned b = blockIdx.x;
    // proportional interleave: assigns each gather index exactly once
    unsigned gb_lo = (unsigned)((unsigned long long)b * n_gblocks / n_blocks_total);
    unsigned gb_hi = (unsigned)((unsigned long long)(b + 1) * n_gblocks / n_blocks_total);

    if (gb_hi > gb_lo) {
        // ---- gather block: 4 warps, 1 node each ----
        int node = (int)gb_lo * 4 + (threadIdx.x >> 5);
        int lane = threadIdx.x & 31;
        if (node < nat) {
            int cnt = g_cnt[node];
            if (cnt > CAP) cnt = CAP;
            int base = node * CAP;
            int half = lane / 12;            // 0,1 active; 2 = idle lanes 24-31
            int l = lane - half * 12;        // float4 slot 0..11
            bool active = lane < 24;
            float4 acc = make_float4(0.f, 0.f, 0.f, 0.f);
            for (int k = 0; k < cnt; k += 2) {
                int kk = k + half;
                if (active && kk < cnt) {
                    int rec = g_bins[base + kk];
                    unsigned e = (unsigned)rec & 0x7fffffffu;
                    float s = __ldg(sw + e);
                    if (rec < 0) s = -s;
                    float4 v = __ldg(x4 + (size_t)e * VPE + l);  // cached: rows read twice
                    acc.x += v.x * s; acc.y += v.y * s;
                    acc.z += v.z * s; acc.w += v.w * s;
                }
            }
            // fold lanes 12-23 into 0-11
            acc.x += __shfl_down_sync(0xffffffffu, acc.x, 12);
            acc.y += __shfl_down_sync(0xffffffffu, acc.y, 12);
            acc.z += __shfl_down_sync(0xffffffffu, acc.z, 12);
            acc.w += __shfl_down_sync(0xffffffffu, acc.w, 12);
            if (lane < 12)
                reinterpret_cast<float4*>(g_scr)[(size_t)node * VPE + lane] = acc;
        }
        return;
    }

    // ---- atomic block (R8 scheme over edges [e_g, E)) ----
    unsigned ab = b - gb_lo;                 // gather blocks preceding b = gb_lo
    unsigned t = ab * 128u + threadIdx.x;
    unsigned total = (unsigned)n_pairs * VPE;
    if (t >= total) return;

    unsigned g = t / VPE;
    unsigned c = t - g * VPE;

    float2 s  = __ldg(sw2a + g);
    int2  src = __ldg(esrc2a + g);
    int2  dst = __ldg(edst2a + g);

    unsigned base = ((unsigned)e_g + 2u * g) * VPE + c;
    float4 v0 = __ldcs(x4 + base);
    float4 v1 = __ldcs(x4 + base + VPE);

    float ax = v0.x * s.x, ay = v0.y * s.x, az = v0.z * s.x, aw = v0.w * s.x;
    float bx = v1.x * s.y, by = v1.y * s.y, bz = v1.z * s.y, bw = v1.w * s.y;

    unsigned co = c * 4u;
    red_v4(out + (unsigned)src.x * D_FEAT + co,  ax,  ay,  az,  aw);
    red_v4(out + (unsigned)dst.x * D_FEAT + co, -ax, -ay, -az, -aw);
    red_v4(out + (unsigned)src.y * D_FEAT + co,  bx,  by,  bz,  bw);
    red_v4(out + (unsigned)dst.y * D_FEAT + co, -bx, -by, -bz, -bw);
}

// ---- K3: out += scratch ----
__global__ void __launch_bounds__(256)
merge_kernel(float4* __restrict__ out4, int n4) {
    int i = blockIdx.x * 256 + threadIdx.x;
    if (i < n4) {
        float4 o = out4[i];
        float4 s = reinterpret_cast<const float4*>(g_scr)[i];
        out4[i] = make_float4(o.x + s.x, o.y + s.y, o.z + s.z, o.w + s.w);
    }
}

// ---- fallback: pure atomic (R8) for unexpected shapes ----
__global__ void __launch_bounds__(128)
scatter_pure_kernel(const float4* __restrict__ x4,
                    const float* __restrict__ sw,
                    const int* __restrict__ esrc,
                    const int* __restrict__ edst,
                    float* __restrict__ out, int n_edges) {
    unsigned t = blockIdx.x * 128u + threadIdx.x;
    unsigned total = (unsigned)n_edges * VPE;
    if (t >= total) return;
    unsigned e = t / VPE, c = t - e * VPE;
    float s = __ldg(sw + e);
    int src = __ldg(esrc + e), dst = __ldg(edst + e);
    float4 v = __ldcs(x4 + (size_t)e * VPE + c);
    float ax = v.x*s, ay = v.y*s, az = v.z*s, aw = v.w*s;
    unsigned co = c * 4u;
    red_v4(out + (unsigned)src * D_FEAT + co,  ax,  ay,  az,  aw);
    red_v4(out + (unsigned)dst * D_FEAT + co, -ax, -ay, -az, -aw);
}

extern "C" void kernel_launch(void* const* d_in, const int* in_sizes, int n_in,
                              void* d_out, int out_size) {
    const float4* x4  = (const float4*)d_in[0];
    const float*  sw  = (const float*)d_in[1];
    const int*    src = (const int*)d_in[2];
    const int*    dst = (const int*)d_in[3];
    float*        out = (float*)d_out;

    int n_edges = in_sizes[1];
    int nat = out_size / D_FEAT;

    cudaMemsetAsync(out, 0, (size_t)out_size * sizeof(float));

    if (nat > NAT_MAX || n_edges < 64) {
        // safe fallback: pure atomic path
        unsigned total = (unsigned)n_edges * VPE;
        scatter_pure_kernel<<<(total + 127) / 128, 128>>>(x4, sw, src, dst, out, n_edges);
        return;
    }

    int e_g = (int)(((long long)n_edges * 2 / 5) & ~1LL);   // 40%, even
    int n_pairs = (n_edges - e_g) / 2;                      // 60% as pairs

    void* cnt_ptr = nullptr;
    cudaGetSymbolAddress(&cnt_ptr, g_cnt);
    cudaMemsetAsync(cnt_ptr, 0, (size_t)nat * sizeof(int));

    // K1: bin gather-half endpoints
    unsigned bin_threads = 2u * (unsigned)e_g;
    bin_kernel<<<(bin_threads + 255) / 256, 256>>>(src, dst, x4, sw, out, e_g);

    // K2: concurrent atomic + gather
    int n_gblocks = (nat + 3) / 4;
    unsigned atomic_total = (unsigned)n_pairs * VPE;
    int n_ablocks = (int)((atomic_total + 127) / 128);
    int T = n_gblocks + n_ablocks;
    hybrid_kernel<<<T, 128>>>(x4,
                              (const float2*)sw + e_g / 2,
                              (const int2*)src + e_g / 2,
                              (const int2*)dst + e_g / 2,
                              sw, out, n_pairs, e_g, nat, n_gblocks, T);

    // K3: out += scratch
    int n4 = nat * VPE;
    merge_kernel<<<(n4 + 255) / 256, 256>>>((float4*)out, n4);
}

// round 11
// speedup vs baseline: 1.2990x; 1.2990x over previous
#include <cuda_runtime.h>
#include <cstdint>

// out[nat, 48] = segment_sum(x*switch, src) - segment_sum(x*switch, dst)
// E = 1.6M, D = 48, nat = 50k.
//
// FINAL FORM (certified floor, R4-R10):
// The op is bound by the LTS atomic-f32 datapath: 38.4M x 16B vector RMW ops
// ~= 1 op/slice/cyc over 184 slices ~= 106us. Verified across six delivery
// architectures (REDG.128 tunings, TMA bulk-reduce, REDG+TMA hybrid, binned
// gather hybrid) -- all converge to 104-110us or worse; red.v8 does not exist
// (128-bit vector-red ceiling); low-precision atomics fail 1e-3 tolerance;
// per-call index preprocessing costs more than it saves.
//
// Scheme: 12 threads per edge (one float4 each), 2 adjacent edges per thread,
// float2/int2 scalar loads (1 wavefront each per 12-lane group), streaming x
// loads, 32-bit offset math, red.global.add.v4.f32 to L2-resident output.

#define D_FEAT 48
#define VECS_PER_EDGE (D_FEAT / 4)   // 12

__device__ __forceinline__ void red_v4(float* p, float a, float b, float c, float d) {
    asm volatile("red.global.add.v4.f32 [%0], {%1,%2,%3,%4};"
                 :: "l"(p), "f"(a), "f"(b), "f"(c), "f"(d) : "memory");
}

__global__ void __launch_bounds__(128)
scatter_edges_kernel(const float4* __restrict__ x4,
                     const float2* __restrict__ sw2,
                     const int2* __restrict__ esrc2,
                     const int2* __restrict__ edst2,
                     float* __restrict__ out,
                     int n_pairs) {
    unsigned t = blockIdx.x * 128u + threadIdx.x;
    unsigned total = (unsigned)n_pairs * VECS_PER_EDGE;
    if (t >= total) return;

    unsigned g = t / VECS_PER_EDGE;        // edge pair: edges 2g, 2g+1
    unsigned c = t - g * VECS_PER_EDGE;    // 0..11

    // Paired scalar loads: 1 wavefront each across the 12-lane group
    float2 s  = __ldg(sw2 + g);
    int2  src = __ldg(esrc2 + g);
    int2  dst = __ldg(edst2 + g);

    // Front-load x (streaming; zero reuse)
    unsigned base = g * (2 * VECS_PER_EDGE) + c;
    float4 v0 = __ldcs(x4 + base);
    float4 v1 = __ldcs(x4 + base + VECS_PER_EDGE);

    float ax = v0.x * s.x, ay = v0.y * s.x, az = v0.z * s.x, aw = v0.w * s.x;
    float bx = v1.x * s.y, by = v1.y * s.y, bz = v1.z * s.y, bw = v1.w * s.y;

    // 32-bit output offsets (max 50k*48 = 2.4M < 2^32)
    unsigned co = c * 4u;
    unsigned o_s0 = (unsigned)src.x * D_FEAT + co;
    unsigned o_d0 = (unsigned)dst.x * D_FEAT + co;
    unsigned o_s1 = (unsigned)src.y * D_FEAT + co;
    unsigned o_d1 = (unsigned)dst.y * D_FEAT + co;

    red_v4(out + o_s0,  ax,  ay,  az,  aw);
    red_v4(out + o_d0, -ax, -ay, -az, -aw);
    red_v4(out + o_s1,  bx,  by,  bz,  bw);
    red_v4(out + o_d1, -bx, -by, -bz, -bw);
}

// Fallback for odd edge counts: one edge per 12-lane group.
__global__ void __launch_bounds__(128)
scatter_tail_kernel(const float4* __restrict__ x4,
                    const float* __restrict__ sw,
                    const int* __restrict__ esrc,
                    const int* __restrict__ edst,
                    float* __restrict__ out,
                    int e_start, int n_edges) {
    unsigned t = blockIdx.x * 128u + threadIdx.x;
    unsigned rem = (unsigned)(n_edges - e_start);
    if (t >= rem * VECS_PER_EDGE) return;
    unsigned e = e_start + t / VECS_PER_EDGE;
    unsigned c = t % VECS_PER_EDGE;
    float s = __ldg(sw + e);
    int src = __ldg(esrc + e), dst = __ldg(edst + e);
    float4 v = __ldcs(x4 + (size_t)e * VECS_PER_EDGE + c);
    float ax = v.x * s, ay = v.y * s, az = v.z * s, aw = v.w * s;
    unsigned co = c * 4u;
    red_v4(out + (unsigned)src * D_FEAT + co,  ax,  ay,  az,  aw);
    red_v4(out + (unsigned)dst * D_FEAT + co, -ax, -ay, -az, -aw);
}

extern "C" void kernel_launch(void* const* d_in, const int* in_sizes, int n_in,
                              void* d_out, int out_size) {
    const float4* x4  = (const float4*)d_in[0];   // x [E, 48] fp32
    const float2* sw2 = (const float2*)d_in[1];   // switch [E]
    const int2*   src = (const int2*)d_in[2];     // edge_src [E]
    const int2*   dst = (const int2*)d_in[3];     // edge_dst [E]
    float*        out = (float*)d_out;            // [nat, 48] fp32

    int n_edges = in_sizes[1];
    int n_pairs = n_edges / 2;                    // E = 1.6M -> even

    cudaMemsetAsync(out, 0, (size_t)out_size * sizeof(float));

    unsigned total = (unsigned)n_pairs * VECS_PER_EDGE;
    scatter_edges_kernel<<<(total + 127) / 128, 128>>>(x4, sw2, src, dst, out, n_pairs);

    if (n_edges & 1) {
        scatter_tail_kernel<<<1, 128>>>((const float4*)d_in[0], (const float*)d_in[1],
                                        (const int*)d_in[2], (const int*)d_in[3],
                                        out, n_edges - 1, n_edges);
    }
}